// round 2
// baseline (speedup 1.0000x reference)
#include <cuda_runtime.h>
#include <math.h>

// ---------------- problem constants ----------------
constexpr int B_  = 8;
constexpr int N_  = 3136;   // H*W
constexpr int C_  = 128;
constexpr int NH_ = 4;
constexpr int D_  = 32;     // C/NH
constexpr int L_  = 9;      // WIN*WIN
constexpr int P_  = 49;     // PH*PW
constexpr int HW_ = 56;     // H == W
constexpr float SCALE_ = 0.08838834764831845f;  // C^-0.5

// ---------------- device scratch (no allocation allowed) ----------------
__device__ __align__(16) float g_kv   [B_*N_*2*C_];   // kv = x @ kv_w.T + b   (25.7 MB)
__device__ __align__(16) float g_srg  [B_*N_*C_];     // gelu(sr(x))           (12.8 MB)
__device__ __align__(16) float g_z    [B_*N_*C_];     // x_local + x_pool
__device__ __align__(16) float g_xacc [B_*N_*C_];     // x_pool per (b,n,c)
__device__ __align__(16) float g_q    [B_*N_*NH_];    // q logits
__device__ __align__(16) float g_ksum [B_*NH_*N_];    // sum_d k
__device__ __align__(16) float g_kpool[B_*NH_*P_];
__device__ __align__(16) float g_vpool[B_*NH_*P_*D_];
__device__ float g_csM[B_*NH_], g_csS[B_*NH_];
__device__ float g_wl [B_*NH_*L_];
__device__ float g_wlf[B_*NH_*L_];
__device__ __align__(16) float g_kvwT [C_*2*C_];      // kv_w transposed (k-major)
__device__ __align__(16) float g_srwT [C_*C_];
__device__ __align__(16) float g_projT[C_*C_];

__device__ __forceinline__ float gelu_exact(float v) {
    return 0.5f * v * (1.0f + erff(v * 0.70710678118654752f));
}

// ---------------- K0: weight transposes ----------------
__global__ void transpose_k(const float* __restrict__ kvw,
                            const float* __restrict__ srw,
                            const float* __restrict__ pjw)
{
    int i = blockIdx.x * 256 + threadIdx.x;        // grid covers 32768
    int o = i >> 7, k = i & 127;
    if (i < 256 * 128) g_kvwT[k * 256 + o] = kvw[i];
    if (i < 128 * 128) { g_srwT[k * 128 + o] = srw[i]; g_projT[k * 128 + o] = pjw[i]; }
}

// ---------------- register-tiled fp32 GEMM template ----------------
// MODE 0: kv = x @ kv_wT (+bias), 256 cols, epilogue also computes q and ksum
// MODE 1: srg = gelu(x @ sr_wT + bias), 128 cols
// MODE 2: out = z @ projT + bias, 128 cols
template<int MODE>
__global__ __launch_bounds__(256) void gemm_k(const float* __restrict__ Xarg,
                                              const float* __restrict__ bias,
                                              float* __restrict__ Outarg,
                                              const float* __restrict__ qw)
{
    constexpr int NCOLS = (MODE == 0) ? 256 : 128;
    constexpr int CT    = NCOLS / 4;        // column-thread count (cols per thread = 4)
    constexpr int RPT   = NCOLS / 32;       // rows per thread (8 or 4)

    const float* __restrict__ X  = (MODE == 2) ? g_z : Xarg;
    const float* __restrict__ WT = (MODE == 0) ? g_kvwT : ((MODE == 1) ? g_srwT : g_projT);
    float* __restrict__ Out      = (MODE == 0) ? g_kv : ((MODE == 1) ? g_srg : Outarg);

    __shared__ __align__(16) float xs[32 * 128];
    int t  = threadIdx.x;
    int cg = t % CT;         // column group (4 consecutive cols)
    int rg = t / CT;         // row group (RPT consecutive rows)
    long row0 = (long)blockIdx.x * 32;

    {
        const float4* X4 = reinterpret_cast<const float4*>(X + row0 * C_);
        float4* xs4 = reinterpret_cast<float4*>(xs);
        #pragma unroll
        for (int i = 0; i < 4; i++) xs4[t + i * 256] = X4[t + i * 256];
    }
    __syncthreads();

    float acc[RPT][4];
    #pragma unroll
    for (int r = 0; r < RPT; r++) { acc[r][0] = acc[r][1] = acc[r][2] = acc[r][3] = 0.f; }

    const float4* W4 = reinterpret_cast<const float4*>(WT) + cg;
    #pragma unroll 4
    for (int k = 0; k < 128; k++) {
        float4 w = __ldg(W4 + k * CT);
        #pragma unroll
        for (int r = 0; r < RPT; r++) {
            float xv = xs[(rg * RPT + r) * 128 + k];   // broadcast LDS
            acc[r][0] = fmaf(xv, w.x, acc[r][0]);
            acc[r][1] = fmaf(xv, w.y, acc[r][1]);
            acc[r][2] = fmaf(xv, w.z, acc[r][2]);
            acc[r][3] = fmaf(xv, w.w, acc[r][3]);
        }
    }

    float4 bb = reinterpret_cast<const float4*>(bias)[cg];
    #pragma unroll
    for (int r = 0; r < RPT; r++) {
        float4 v;
        v.x = acc[r][0] + bb.x; v.y = acc[r][1] + bb.y;
        v.z = acc[r][2] + bb.z; v.w = acc[r][3] + bb.w;
        if (MODE == 1) {
            v.x = gelu_exact(v.x); v.y = gelu_exact(v.y);
            v.z = gelu_exact(v.z); v.w = gelu_exact(v.w);
        }
        reinterpret_cast<float4*>(Out + (row0 + rg * RPT + r) * NCOLS)[cg] = v;
    }

    if (MODE == 0) {
        __syncthreads();   // kv global stores visible within block
        if (t < 128) {
            int r = t >> 2, h = t & 3;
            long grow = row0 + r;
            // q logits (bias/query_embedding cancel in softmax over n)
            float s = 0.f;
            #pragma unroll 8
            for (int k = 0; k < 128; k++) s = fmaf(xs[r * 128 + k], qw[h * 128 + k], s);
            g_q[grow * NH_ + h] = s;
            // ksum = sum_d k[head h]
            const float4* kvr = reinterpret_cast<const float4*>(Out + grow * 256 + h * 32);
            float ks = 0.f;
            #pragma unroll
            for (int j = 0; j < 8; j++) { float4 a = kvr[j]; ks += a.x + a.y + a.z + a.w; }
            int b = (int)(grow / N_), n = (int)(grow % N_);
            g_ksum[((long)b * NH_ + h) * N_ + n] = ks;
        }
    }
}

// ---------------- K2b: 8x8 avg-pool + layernorm + kvp -> k_pool / v_pool ----------------
__global__ __launch_bounds__(128) void pool_k(const float* __restrict__ nw,
                                              const float* __restrict__ nb,
                                              const float* __restrict__ kvb)
{
    int b = blockIdx.x / P_, p = blockIdx.x % P_;
    int py = p / 7, px = p % 7;
    int c = threadIdx.x, lane = c & 31, wid = c >> 5;

    float s = 0.f;
    for (int pix = 0; pix < 64; pix++) {
        int n = (py * 8 + (pix >> 3)) * HW_ + px * 8 + (pix & 7);
        s += g_srg[((long)b * N_ + n) * C_ + c];
    }
    s *= (1.f / 64.f);

    __shared__ float sh[4];
    float v = s;
    #pragma unroll
    for (int o = 16; o; o >>= 1) v += __shfl_xor_sync(~0u, v, o);
    if (lane == 0) sh[wid] = v;
    __syncthreads();
    float mu = (sh[0] + sh[1] + sh[2] + sh[3]) * (1.f / C_);
    float d  = s - mu;
    __syncthreads();
    v = d * d;
    #pragma unroll
    for (int o = 16; o; o >>= 1) v += __shfl_xor_sync(~0u, v, o);
    if (lane == 0) sh[wid] = v;
    __syncthreads();
    float var = (sh[0] + sh[1] + sh[2] + sh[3]) * (1.f / C_);
    float xn  = d * rsqrtf(var + 1e-5f) * nw[c] + nb[c];

    __shared__ float xsn[C_];
    __shared__ float kvs[2 * C_];
    xsn[c] = xn;
    __syncthreads();

    #pragma unroll
    for (int j = 0; j < 2; j++) {
        int o = c + j * C_;
        float a = kvb[o];
        #pragma unroll 8
        for (int k = 0; k < C_; k++) a = fmaf(g_kvwT[k * 256 + o], xsn[k], a);
        kvs[o] = a;
    }
    __syncthreads();

    if (c < NH_) {
        float kp = 0.f;
        #pragma unroll
        for (int d2 = 0; d2 < D_; d2++) kp += kvs[c * D_ + d2];
        g_kpool[(b * NH_ + c) * P_ + p] = kp;
    }
    g_vpool[((b * NH_ + (c >> 5)) * P_ + p) * D_ + (c & 31)] = kvs[C_ + c];
}

// ---------------- K3: context-score softmax stats over n (per b,h) ----------------
__global__ __launch_bounds__(256) void cs_stats_k()
{
    int bh = blockIdx.x;
    int b  = bh >> 2, h = bh & 3;
    int t = threadIdx.x, lane = t & 31, wid = t >> 5;
    __shared__ float sh[8];
    const float* qp = g_q + (long)b * N_ * NH_ + h;

    float m = -INFINITY;
    for (int n = t; n < N_; n += 256) m = fmaxf(m, qp[n * NH_]);
    #pragma unroll
    for (int o = 16; o; o >>= 1) m = fmaxf(m, __shfl_xor_sync(~0u, m, o));
    if (lane == 0) sh[wid] = m;
    __syncthreads();
    float M = sh[0];
    #pragma unroll
    for (int w = 1; w < 8; w++) M = fmaxf(M, sh[w]);
    __syncthreads();

    float s = 0.f;
    for (int n = t; n < N_; n += 256) s += expf(qp[n * NH_] - M);
    #pragma unroll
    for (int o = 16; o; o >>= 1) s += __shfl_xor_sync(~0u, s, o);
    if (lane == 0) sh[wid] = s;
    __syncthreads();
    if (t == 0) {
        float S = 0.f;
        #pragma unroll
        for (int w = 0; w < 8; w++) S += sh[w];
        g_csM[bh] = M;
        g_csS[bh] = 1.f / S;
    }
    if (t < L_) g_wl[bh * L_ + t] = 0.f;   // zero a_local accumulator for K4 atomics
}

// ---------------- K4: per-n 58-way softmax + pool matvec + a_local reduction ----------------
// grid: (49 n-tiles of 64, 32 bh), 256 threads = 8 warps, warp handles 8 n's.
__global__ __launch_bounds__(256) void attn_k(const float* __restrict__ pbp,
                                              const float* __restrict__ pbl)
{
    int bh = blockIdx.y;
    int b  = bh >> 2, h = bh & 3;
    int n0 = blockIdx.x * 64;
    int t = threadIdx.x, lane = t & 31, wid = t >> 5;

    __shared__ float vps[P_ * D_];
    __shared__ float kps[P_];
    __shared__ float asb[8][64];
    __shared__ float wlsh[8][L_];
    __shared__ float msh[2];

    for (int i = t; i < P_ * D_; i += 256) vps[i] = g_vpool[bh * P_ * D_ + i];
    if (t < P_) kps[t] = g_kpool[bh * P_ + t];
    if (t == 0) { msh[0] = g_csM[bh]; msh[1] = g_csS[bh]; }
    __syncthreads();

    float M = msh[0], invS = msh[1];
    const float NEG = -INFINITY;
    float wlacc = 0.f;
    float pbl_l = (lane < L_) ? pbl[h * L_ + lane] : 0.f;

    for (int i = 0; i < 8; i++) {
        int n = n0 + wid * 8 + i;
        float cs  = expf(g_q[((long)b * N_ + n) * NH_ + h] - M) * invS;
        float csS = cs * SCALE_;
        const float* pbpn = pbp + ((long)h * N_ + n) * P_;

        // slot s0 = lane (0..8 local, 9..31 pool p=lane-9); slot s1 = lane+32 (pool p=lane+23)
        float v0, v1 = NEG;
        if (lane < L_) {
            int y = n / HW_ + lane / 3 - 1, x = n % HW_ + lane % 3 - 1;
            v0 = (y >= 0 && y < HW_ && x >= 0 && x < HW_)
                 ? g_ksum[(long)bh * N_ + y * HW_ + x] * csS + pbl_l : NEG;
        } else {
            int p = lane - L_;
            v0 = csS * kps[p] + pbpn[p];
        }
        if (lane < 26) { int p = lane + 23; v1 = csS * kps[p] + pbpn[p]; }

        float mx = fmaxf(v0, v1);
        #pragma unroll
        for (int o = 16; o; o >>= 1) mx = fmaxf(mx, __shfl_xor_sync(0xffffffffu, mx, o));
        float e0 = expf(v0 - mx);
        float e1 = (lane < 26) ? expf(v1 - mx) : 0.f;
        float se = e0 + e1;
        #pragma unroll
        for (int o = 16; o; o >>= 1) se += __shfl_xor_sync(0xffffffffu, se, o);
        float inv = 1.f / se;
        e0 *= inv; e1 *= inv;

        if (lane < L_) wlacc += e0;                 // sum_n a_local
        asb[wid][lane] = e0;
        if (lane < 26) asb[wid][lane + 32] = e1;
        __syncwarp();

        // x_pool[d=lane] = sum_p a_pool[p] * v_pool[p][d]
        float acc = 0.f;
        #pragma unroll
        for (int p = 0; p < P_; p++)
            acc = fmaf(asb[wid][L_ + p], vps[p * D_ + lane], acc);
        g_xacc[((long)b * N_ + n) * C_ + h * D_ + lane] = acc;
        __syncwarp();
    }

    if (lane < L_) wlsh[wid][lane] = wlacc;
    __syncthreads();
    if (t < L_) {
        float s = 0.f;
        #pragma unroll
        for (int w = 0; w < 8; w++) s += wlsh[w][t];
        atomicAdd(&g_wl[bh * L_ + t], s);
    }
}

// ---------------- K4b: finalize w_local ----------------
__global__ void wlfinal_k(const float* __restrict__ lt, const float* __restrict__ lb)
{
    int i = blockIdx.x * 256 + threadIdx.x;
    if (i < B_ * NH_ * L_) {
        int l = i % L_, h = (i / L_) & 3;
        g_wlf[i] = lt[h * L_ + l] + (float)N_ * lb[h * L_ + l] + g_wl[i];
    }
}

// ---------------- K5a: z = x_pool + sum_l relu(v[nb(n,l)]) * w_local ----------------
__global__ __launch_bounds__(256) void localmix_k()
{
    long e = (long)blockIdx.x * 256 + threadIdx.x;   // exact: B*N*C elements
    int  c  = (int)(e & (C_ - 1));
    long gr = e >> 7;
    int  b  = (int)(gr / N_), n = (int)(gr % N_);
    int  h  = c >> 5;
    float y = g_xacc[e];
    int yy = n / HW_, xx = n % HW_;
    const float* wf = g_wlf + (b * NH_ + h) * L_;
    #pragma unroll
    for (int l = 0; l < L_; l++) {
        int py = yy + l / 3 - 1, px = xx + l % 3 - 1;
        if (py >= 0 && py < HW_ && px >= 0 && px < HW_) {
            float v = g_kv[((long)b * N_ + py * HW_ + px) * (2 * C_) + C_ + c];
            y = fmaf(fmaxf(v, 0.f), wf[l], y);
        }
    }
    g_z[e] = y;
}

// ---------------- launch ----------------
extern "C" void kernel_launch(void* const* d_in, const int* in_sizes, int n_in,
                              void* d_out, int out_size)
{
    const float* x    = (const float*)d_in[0];
    const float* q_w  = (const float*)d_in[1];
    // d_in[2] q_b, d_in[3] query_embedding: cancel in softmax over n — unused
    const float* kv_w = (const float*)d_in[4];
    const float* kv_b = (const float*)d_in[5];
    const float* sr_w = (const float*)d_in[6];
    const float* sr_b = (const float*)d_in[7];
    const float* nw   = (const float*)d_in[8];
    const float* nb   = (const float*)d_in[9];
    const float* pbp  = (const float*)d_in[10];
    const float* pbl  = (const float*)d_in[11];
    const float* lt   = (const float*)d_in[12];
    const float* lb   = (const float*)d_in[13];
    const float* pjw  = (const float*)d_in[14];
    const float* pjb  = (const float*)d_in[15];
    float* out = (float*)d_out;

    transpose_k<<<128, 256>>>(kv_w, sr_w, pjw);
    gemm_k<0><<<784, 256>>>(x, kv_b, nullptr, q_w);     // kv + q + ksum
    gemm_k<1><<<784, 256>>>(x, sr_b, nullptr, nullptr); // gelu(sr(x))
    pool_k<<<B_ * P_, 128>>>(nw, nb, kv_b);             // pool + LN + kvp
    cs_stats_k<<<B_ * NH_, 256>>>();                    // context softmax stats
    dim3 g4(49, B_ * NH_);
    attn_k<<<g4, 256>>>(pbp, pbl);                      // 58-way softmax + x_pool
    wlfinal_k<<<2, 256>>>(lt, lb);
    localmix_k<<<12544, 256>>>();                       // z = x_pool + local
    gemm_k<2><<<784, 256>>>(nullptr, pjb, out, nullptr); // projection
}